// round 2
// baseline (speedup 1.0000x reference)
#include <cuda_runtime.h>
#include <math_constants.h>

// ============================================================================
// Chamfer loss via exact uniform-grid nearest-neighbor search.
//   1) k_init : zero cell counts / extras / bbox / out
//   2) k_bbox : bounding box of both clouds (warp-reduced ordered-int atomics)
//   3) k_bin  : bin every point into G x G square-cell grid (CAP slots/cell,
//               overflow -> extras list, so search stays EXACT regardless)
//   4) k_query: expanding-ring exact NN per query, stop when
//               best_d2 <= ((r-1)*cs)^2 before scanning ring r;
//               d = sqrt(best_d2), block-reduced sum -> atomicAdd(out)
// ============================================================================

#define G      256
#define NCELL  (G * G)
#define CAP    32
#define EMAX   16384
#define TPB    256

__device__ unsigned g_bbox[4];              // ordered-int: minx,miny,maxx,maxy
__device__ int      g_cnt[2][NCELL];
__device__ int      g_ecnt[2];
__device__ float2   g_bkt[2][NCELL * CAP];
__device__ float2   g_ext[2][EMAX];

// Order-preserving float <-> uint map (valid for all finite floats).
static __device__ __forceinline__ unsigned f2ord(float f) {
    int b = __float_as_int(f);
    return (unsigned)b ^ (b < 0 ? 0xFFFFFFFFu : 0x80000000u);
}
static __device__ __forceinline__ float ord2f(unsigned u) {
    int b = (u & 0x80000000u) ? (int)(u ^ 0x80000000u) : (int)(~u);
    return __int_as_float(b);
}

// ---------------------------------------------------------------------------
__global__ void k_init(float* __restrict__ out) {
    int i = blockIdx.x * blockDim.x + threadIdx.x;
    if (i < 2 * NCELL) ((int*)g_cnt)[i] = 0;
    if (i == 0) {
        out[0] = 0.0f;
        g_ecnt[0] = 0; g_ecnt[1] = 0;
        g_bbox[0] = 0xFFFFFFFFu;  // min x
        g_bbox[1] = 0xFFFFFFFFu;  // min y
        g_bbox[2] = 0u;           // max x
        g_bbox[3] = 0u;           // max y
    }
}

// ---------------------------------------------------------------------------
__global__ void k_bbox(const float* __restrict__ A, int na,
                       const float* __restrict__ B, int nb) {
    int i = blockIdx.x * blockDim.x + threadIdx.x;
    int total = na + nb;
    unsigned mnx = 0xFFFFFFFFu, mny = 0xFFFFFFFFu, mxx = 0u, mxy = 0u;
    if (i < total) {
        const float* P = (i < na) ? (A + 2 * i) : (B + 2 * (i - na));
        unsigned ux = f2ord(P[0]), uy = f2ord(P[1]);
        mnx = ux; mny = uy; mxx = ux; mxy = uy;
    }
#pragma unroll
    for (int off = 16; off > 0; off >>= 1) {
        mnx = min(mnx, __shfl_down_sync(0xFFFFFFFFu, mnx, off));
        mny = min(mny, __shfl_down_sync(0xFFFFFFFFu, mny, off));
        mxx = max(mxx, __shfl_down_sync(0xFFFFFFFFu, mxx, off));
        mxy = max(mxy, __shfl_down_sync(0xFFFFFFFFu, mxy, off));
    }
    if ((threadIdx.x & 31) == 0) {
        atomicMin(&g_bbox[0], mnx);
        atomicMin(&g_bbox[1], mny);
        atomicMax(&g_bbox[2], mxx);
        atomicMax(&g_bbox[3], mxy);
    }
}

// ---------------------------------------------------------------------------
static __device__ __forceinline__ void grid_params(float& x0, float& y0,
                                                   float& cs, float& inv) {
    x0 = ord2f(g_bbox[0]);
    y0 = ord2f(g_bbox[1]);
    float L = fmaxf(ord2f(g_bbox[2]) - x0, ord2f(g_bbox[3]) - y0);
    L = fmaxf(L, 1e-20f);
    cs = L / (float)G;
    inv = (float)G / L;
}

__global__ void k_bin(const float* __restrict__ A, int na,
                      const float* __restrict__ B, int nb) {
    int i = blockIdx.x * blockDim.x + threadIdx.x;
    int total = na + nb;
    if (i >= total) return;
    int s = (i < na) ? 0 : 1;
    const float* P = (s == 0) ? (A + 2 * i) : (B + 2 * (i - na));
    float x = P[0], y = P[1];

    float x0, y0, cs, inv;
    grid_params(x0, y0, cs, inv);
    int cx = min(G - 1, max(0, (int)((x - x0) * inv)));
    int cy = min(G - 1, max(0, (int)((y - y0) * inv)));
    int c = cy * G + cx;

    int pos = atomicAdd(&g_cnt[s][c], 1);
    if (pos < CAP) {
        g_bkt[s][c * CAP + pos] = make_float2(x, y);
    } else {
        int e = atomicAdd(&g_ecnt[s], 1);
        if (e < EMAX) g_ext[s][e] = make_float2(x, y);
    }
}

// ---------------------------------------------------------------------------
__global__ __launch_bounds__(TPB) void k_query(const float* __restrict__ A, int na,
                                               const float* __restrict__ B, int nb,
                                               float* __restrict__ out) {
    int i = blockIdx.x * blockDim.x + threadIdx.x;
    int total = na + nb;
    float d = 0.0f;

    if (i < total) {
        int s = (i < na) ? 0 : 1;   // query set
        int t = s ^ 1;              // target set
        const float* P = (s == 0) ? (A + 2 * i) : (B + 2 * (i - na));
        float qx = P[0], qy = P[1];

        float x0, y0, cs, inv;
        grid_params(x0, y0, cs, inv);
        int cx = min(G - 1, max(0, (int)((qx - x0) * inv)));
        int cy = min(G - 1, max(0, (int)((qy - y0) * inv)));

        float best = CUDART_INF_F;

        // Overflow extras (normally empty) — keeps search exact under any load.
        int ne = min(g_ecnt[t], EMAX);
        for (int e = 0; e < ne; e++) {
            float2 p = g_ext[t][e];
            float dx = qx - p.x, dy = qy - p.y;
            best = fminf(best, fmaf(dx, dx, dy * dy));
        }

        auto scan_cell = [&](int xx, int yy) {
            int c = yy * G + xx;
            int n = min(g_cnt[t][c], CAP);
            const float2* bp = &g_bkt[t][c * CAP];
            for (int k = 0; k < n; k++) {
                float2 p = bp[k];
                float dx = qx - p.x, dy = qy - p.y;
                best = fminf(best, fmaf(dx, dx, dy * dy));
            }
        };

        for (int r = 0; r < G; r++) {
            if (r > 0) {
                // Everything in rings >= r is at distance >= (r-1)*cs.
                float b = (float)(r - 1) * cs;
                if (best <= b * b) break;
            }
            if (r == 0) {
                scan_cell(cx, cy);
            } else {
                int xlo = max(cx - r, 0), xhi = min(cx + r, G - 1);
                if (cy - r >= 0)
                    for (int xx = xlo; xx <= xhi; xx++) scan_cell(xx, cy - r);
                if (cy + r <= G - 1)
                    for (int xx = xlo; xx <= xhi; xx++) scan_cell(xx, cy + r);
                int ylo = max(cy - r + 1, 0), yhi = min(cy + r - 1, G - 1);
                if (cx - r >= 0)
                    for (int yy = ylo; yy <= yhi; yy++) scan_cell(cx - r, yy);
                if (cx + r <= G - 1)
                    for (int yy = ylo; yy <= yhi; yy++) scan_cell(cx + r, yy);
            }
        }
        d = sqrtf(best);
    }

    // Block reduction -> one atomicAdd per block.
#pragma unroll
    for (int off = 16; off > 0; off >>= 1)
        d += __shfl_down_sync(0xFFFFFFFFu, d, off);
    __shared__ float ws[TPB / 32];
    int lane = threadIdx.x & 31, wid = threadIdx.x >> 5;
    if (lane == 0) ws[wid] = d;
    __syncthreads();
    if (wid == 0) {
        d = (lane < TPB / 32) ? ws[lane] : 0.0f;
#pragma unroll
        for (int off = 4; off > 0; off >>= 1)
            d += __shfl_down_sync(0xFFFFFFFFu, d, off);
        if (lane == 0) atomicAdd(out, d);
    }
}

// ---------------------------------------------------------------------------
extern "C" void kernel_launch(void* const* d_in, const int* in_sizes, int n_in,
                              void* d_out, int out_size) {
    const float* A = (const float*)d_in[0];   // img_render_points (16384 x 2)
    const float* B = (const float*)d_in[1];   // ref cloud (16384 x 2)
    int na = in_sizes[0] / 2;
    int nb = in_sizes[1] / 2;
    int total = na + nb;
    float* out = (float*)d_out;

    k_init<<<(2 * NCELL + TPB - 1) / TPB, TPB>>>(out);
    k_bbox<<<(total + TPB - 1) / TPB, TPB>>>(A, na, B, nb);
    k_bin <<<(total + TPB - 1) / TPB, TPB>>>(A, na, B, nb);
    k_query<<<(total + TPB - 1) / TPB, TPB>>>(A, na, B, nb, out);
}

// round 3
// speedup vs baseline: 2.9258x; 2.9258x over previous
#include <cuda_runtime.h>
#include <math_constants.h>

// ============================================================================
// Chamfer loss via exact uniform-grid NN, CSR-sorted points.
//   k_bbox : per-block bbox partials (no atomics) + zero counts + zero out
//   k_count: reduce bbox, bin points -> cell counts + cell ids
//   k_scan : single-block exclusive scan of 2x16384 cell counts (CSR offsets),
//            re-zero counts (reused as fill cursors)
//   k_fill : scatter points into CSR-sorted order
//   k_query: iterate SORTED points (warp-coherent), scan 3x3 neighborhood as
//            3 contiguous CSR segments, expand rings only if bound not met
//            (exact: unscanned cells at Chebyshev ring k are >= (k-1)*cs away)
// ============================================================================

#define G       128
#define NCELL   (G * G)
#define NMAX    16384
#define TPB     256
#define TPBQ    128
#define MAXBLK  256

__device__ unsigned g_blkbox[MAXBLK][4];     // per-block minx,miny,maxx,maxy (ordered uint)
__device__ int      g_cnt[2][NCELL];         // counts, then fill cursors
__device__ int      g_off[2][NCELL + 1];     // CSR offsets
__device__ int      g_cid[2][NMAX];          // cell id per original point
__device__ float2   g_pts[2][NMAX];          // CSR-sorted points

static __device__ __forceinline__ unsigned f2ord(float f) {
    int b = __float_as_int(f);
    return (unsigned)b ^ (b < 0 ? 0xFFFFFFFFu : 0x80000000u);
}
static __device__ __forceinline__ float ord2f(unsigned u) {
    int b = (u & 0x80000000u) ? (int)(u ^ 0x80000000u) : (int)(~u);
    return __int_as_float(b);
}

// Reduce per-block bbox partials -> grid params. Needs blockDim>=32 and a
// subsequent __syncthreads (included). All threads must reach this.
static __device__ __forceinline__ void load_grid(int nblk, float& x0, float& y0,
                                                 float& cs, float& inv) {
    __shared__ unsigned sbb[4];
    if (threadIdx.x < 32) {
        unsigned mnx = 0xFFFFFFFFu, mny = 0xFFFFFFFFu, mxx = 0u, mxy = 0u;
        for (int b = threadIdx.x; b < nblk; b += 32) {
            mnx = min(mnx, g_blkbox[b][0]);
            mny = min(mny, g_blkbox[b][1]);
            mxx = max(mxx, g_blkbox[b][2]);
            mxy = max(mxy, g_blkbox[b][3]);
        }
#pragma unroll
        for (int off = 16; off > 0; off >>= 1) {
            mnx = min(mnx, __shfl_down_sync(0xFFFFFFFFu, mnx, off));
            mny = min(mny, __shfl_down_sync(0xFFFFFFFFu, mny, off));
            mxx = max(mxx, __shfl_down_sync(0xFFFFFFFFu, mxx, off));
            mxy = max(mxy, __shfl_down_sync(0xFFFFFFFFu, mxy, off));
        }
        if (threadIdx.x == 0) { sbb[0] = mnx; sbb[1] = mny; sbb[2] = mxx; sbb[3] = mxy; }
    }
    __syncthreads();
    x0 = ord2f(sbb[0]);
    y0 = ord2f(sbb[1]);
    float L = fmaxf(ord2f(sbb[2]) - x0, ord2f(sbb[3]) - y0);
    L = fmaxf(L, 1e-20f);
    cs = L / (float)G;
    inv = (float)G / L;
}

static __device__ __forceinline__ int cell_of(float v, float o, float inv) {
    return min(G - 1, max(0, (int)((v - o) * inv)));
}

// ---------------------------------------------------------------------------
__global__ void k_bbox(const float* __restrict__ A, int na,
                       const float* __restrict__ B, int nb,
                       float* __restrict__ out) {
    int i = blockIdx.x * blockDim.x + threadIdx.x;
    int total = na + nb;
    // zero counts (independent memory; no ordering hazard)
    for (int j = i; j < 2 * NCELL; j += gridDim.x * blockDim.x)
        ((int*)g_cnt)[j] = 0;
    if (i == 0) out[0] = 0.0f;

    unsigned mnx = 0xFFFFFFFFu, mny = 0xFFFFFFFFu, mxx = 0u, mxy = 0u;
    if (i < total) {
        const float* P = (i < na) ? (A + 2 * i) : (B + 2 * (i - na));
        unsigned ux = f2ord(P[0]), uy = f2ord(P[1]);
        mnx = ux; mny = uy; mxx = ux; mxy = uy;
    }
#pragma unroll
    for (int off = 16; off > 0; off >>= 1) {
        mnx = min(mnx, __shfl_down_sync(0xFFFFFFFFu, mnx, off));
        mny = min(mny, __shfl_down_sync(0xFFFFFFFFu, mny, off));
        mxx = max(mxx, __shfl_down_sync(0xFFFFFFFFu, mxx, off));
        mxy = max(mxy, __shfl_down_sync(0xFFFFFFFFu, mxy, off));
    }
    __shared__ unsigned sw[4][TPB / 32];
    int lane = threadIdx.x & 31, wid = threadIdx.x >> 5;
    if (lane == 0) { sw[0][wid] = mnx; sw[1][wid] = mny; sw[2][wid] = mxx; sw[3][wid] = mxy; }
    __syncthreads();
    if (wid == 0 && lane < TPB / 32) {
        mnx = sw[0][lane]; mny = sw[1][lane]; mxx = sw[2][lane]; mxy = sw[3][lane];
#pragma unroll
        for (int off = 4; off > 0; off >>= 1) {
            mnx = min(mnx, __shfl_down_sync(0xFFu, mnx, off));
            mny = min(mny, __shfl_down_sync(0xFFu, mny, off));
            mxx = max(mxx, __shfl_down_sync(0xFFu, mxx, off));
            mxy = max(mxy, __shfl_down_sync(0xFFu, mxy, off));
        }
        if (lane == 0) {
            g_blkbox[blockIdx.x][0] = mnx; g_blkbox[blockIdx.x][1] = mny;
            g_blkbox[blockIdx.x][2] = mxx; g_blkbox[blockIdx.x][3] = mxy;
        }
    }
}

// ---------------------------------------------------------------------------
__global__ void k_count(const float* __restrict__ A, int na,
                        const float* __restrict__ B, int nb, int nblk) {
    float x0, y0, cs, inv;
    load_grid(nblk, x0, y0, cs, inv);
    int i = blockIdx.x * blockDim.x + threadIdx.x;
    int total = na + nb;
    if (i >= total) return;
    int s = (i < na) ? 0 : 1;
    int q = (i < na) ? i : i - na;
    const float* P = (s == 0) ? (A + 2 * q) : (B + 2 * q);
    int c = cell_of(P[1], y0, inv) * G + cell_of(P[0], x0, inv);
    g_cid[s][q] = c;
    atomicAdd(&g_cnt[s][c], 1);
}

// ---------------------------------------------------------------------------
#define SCANT 1024
#define CPT   (NCELL / SCANT)   // 16
__global__ __launch_bounds__(SCANT) void k_scan(int na, int nb) {
    __shared__ int sm[SCANT];
    int tid = threadIdx.x;
    for (int s = 0; s < 2; s++) {
        int base = tid * CPT;
        int loc[CPT];
        int sum = 0;
#pragma unroll
        for (int k = 0; k < CPT; k++) { loc[k] = g_cnt[s][base + k]; sum += loc[k]; }
        sm[tid] = sum;
        __syncthreads();
        int acc = sum;
        for (int d = 1; d < SCANT; d <<= 1) {
            int v = (tid >= d) ? sm[tid - d] : 0;
            __syncthreads();
            acc += v;
            sm[tid] = acc;
            __syncthreads();
        }
        int run = acc - sum;  // exclusive
#pragma unroll
        for (int k = 0; k < CPT; k++) {
            g_off[s][base + k] = run;
            run += loc[k];
            g_cnt[s][base + k] = 0;   // cursor for fill
        }
        if (tid == SCANT - 1) g_off[s][NCELL] = run;
        __syncthreads();
    }
}

// ---------------------------------------------------------------------------
__global__ void k_fill(const float* __restrict__ A, int na,
                       const float* __restrict__ B, int nb) {
    int i = blockIdx.x * blockDim.x + threadIdx.x;
    int total = na + nb;
    if (i >= total) return;
    int s = (i < na) ? 0 : 1;
    int q = (i < na) ? i : i - na;
    const float* P = (s == 0) ? (A + 2 * q) : (B + 2 * q);
    int c = g_cid[s][q];
    int pos = g_off[s][c] + atomicAdd(&g_cnt[s][c], 1);
    g_pts[s][pos] = make_float2(P[0], P[1]);
}

// ---------------------------------------------------------------------------
__global__ __launch_bounds__(TPBQ) void k_query(int na, int nb, int nblk,
                                                float* __restrict__ out) {
    float x0, y0, cs, inv;
    load_grid(nblk, x0, y0, cs, inv);

    int i = blockIdx.x * blockDim.x + threadIdx.x;
    int total = na + nb;
    float d = 0.0f;

    if (i < total) {
        int s = (i < na) ? 0 : 1;
        int q = (i < na) ? i : i - na;
        int t = s ^ 1;
        float2 Q = g_pts[s][q];          // sorted order -> warp-coherent cells
        float qx = Q.x, qy = Q.y;
        int cx = cell_of(qx, x0, inv);
        int cy = cell_of(qy, y0, inv);

        const int*    __restrict__ off = g_off[t];
        const float2* __restrict__ pts = g_pts[t];
        float best = CUDART_INF_F;

        auto scan_seg = [&](int s0, int e0) {
            for (int k = s0; k < e0; k++) {
                float2 p = pts[k];
                float dx = qx - p.x, dy = qy - p.y;
                best = fminf(best, fmaf(dx, dx, dy * dy));
            }
        };

        // Rings 0..1 (3x3) unconditionally: 3 contiguous row segments.
        {
            int xlo = max(cx - 1, 0), xhi = min(cx + 1, G - 1);
            int s0 = 0, e0 = 0, s1 = 0, e1 = 0, s2 = 0, e2 = 0;
            if (cy - 1 >= 0)    { s0 = off[(cy - 1) * G + xlo]; e0 = off[(cy - 1) * G + xhi + 1]; }
            { s1 = off[cy * G + xlo]; e1 = off[cy * G + xhi + 1]; }
            if (cy + 1 <= G - 1){ s2 = off[(cy + 1) * G + xlo]; e2 = off[(cy + 1) * G + xhi + 1]; }
            scan_seg(s0, e0);
            scan_seg(s1, e1);
            scan_seg(s2, e2);
        }

        // Ring expansion (rare): before ring r, unscanned pts >= (r-1)*cs away.
        for (int r = 2; r < G; r++) {
            float b = (float)(r - 1) * cs;
            if (best <= b * b) break;
            int xlo = max(cx - r, 0), xhi = min(cx + r, G - 1);
            if (cy - r >= 0) {
                int row = (cy - r) * G;
                scan_seg(off[row + xlo], off[row + xhi + 1]);
            }
            if (cy + r <= G - 1) {
                int row = (cy + r) * G;
                scan_seg(off[row + xlo], off[row + xhi + 1]);
            }
            int ylo = max(cy - r + 1, 0), yhi = min(cy + r - 1, G - 1);
            if (cx - r >= 0)
                for (int yy = ylo; yy <= yhi; yy++)
                    scan_seg(off[yy * G + cx - r], off[yy * G + cx - r + 1]);
            if (cx + r <= G - 1)
                for (int yy = ylo; yy <= yhi; yy++)
                    scan_seg(off[yy * G + cx + r], off[yy * G + cx + r + 1]);
        }
        d = sqrtf(best);
    }

    // Block sum -> one atomicAdd per block.
#pragma unroll
    for (int off = 16; off > 0; off >>= 1)
        d += __shfl_down_sync(0xFFFFFFFFu, d, off);
    __shared__ float ws[TPBQ / 32];
    int lane = threadIdx.x & 31, wid = threadIdx.x >> 5;
    if (lane == 0) ws[wid] = d;
    __syncthreads();
    if (wid == 0) {
        d = (lane < TPBQ / 32) ? ws[lane] : 0.0f;
#pragma unroll
        for (int off = TPBQ / 64; off > 0; off >>= 1)
            d += __shfl_down_sync(0xFFFFFFFFu, d, off);
        if (lane == 0) atomicAdd(out, d);
    }
}

// ---------------------------------------------------------------------------
extern "C" void kernel_launch(void* const* d_in, const int* in_sizes, int n_in,
                              void* d_out, int out_size) {
    const float* A = (const float*)d_in[0];
    const float* B = (const float*)d_in[1];
    int na = in_sizes[0] / 2;
    int nb = in_sizes[1] / 2;
    int total = na + nb;
    float* out = (float*)d_out;

    int nblk = (total + TPB - 1) / TPB;
    if (nblk > MAXBLK) nblk = MAXBLK;   // fixed sizes: 32768/256 = 128

    k_bbox <<<nblk, TPB>>>(A, na, B, nb, out);
    k_count<<<nblk, TPB>>>(A, na, B, nb, nblk);
    k_scan <<<1, SCANT>>>(na, nb);
    k_fill <<<nblk, TPB>>>(A, na, B, nb);
    k_query<<<(total + TPBQ - 1) / TPBQ, TPBQ>>>(na, nb, nblk, out);
}

// round 5
// speedup vs baseline: 4.1943x; 1.4336x over previous
#include <cuda_runtime.h>
#include <math_constants.h>

// ============================================================================
// Chamfer loss: ONE persistent kernel, exact uniform-grid NN with CSR layout.
// Grid = #SMs (all CTAs co-resident) with software grid barriers.
// Phases: P0 bbox partials + zero counts  | P1 bin (cell id + rank)
//         P2 per-block chunk scan         | P3 block bases -> CSR offsets
//         P4 scatter fill (sorted points) | P5 query (4 lanes/query, exact
//         ring expansion: unscanned cells at Chebyshev ring r are >=(r-1)*cs)
// R4 fix: all __shfl_*_sync masks now exactly match executing lane sets
// (previous round had an 8-lane guard with a 32-lane mask -> warp deadlock).
// ============================================================================

#define G      128
#define NCELL  (G * G)
#define TC     (2 * NCELL)        // combined cells (set0 then set1)
#define TMAX   65536              // max total points supported
#define TPB    256
#define NW     (TPB / 32)
#define MAXBLK 256

__device__ int          g_arr;
__device__ volatile int g_gen;
__device__ unsigned     g_blkbox[MAXBLK][4];
__device__ int          g_blksum[MAXBLK];
__device__ int          g_cnt[TC];
__device__ int          g_off[TC + 1];
__device__ int          g_cid[TMAX];
__device__ int          g_rank[TMAX];
__device__ float2       g_pts[TMAX];

static __device__ __forceinline__ unsigned f2ord(float f) {
    int b = __float_as_int(f);
    return (unsigned)b ^ (b < 0 ? 0xFFFFFFFFu : 0x80000000u);
}
static __device__ __forceinline__ float ord2f(unsigned u) {
    int b = (u & 0x80000000u) ? (int)(u ^ 0x80000000u) : (int)(~u);
    return __int_as_float(b);
}

// Grid-wide barrier: all CTAs co-resident (grid <= #SMs). Monotonic generation
// counter -> safe across graph replays.
static __device__ __forceinline__ void gridbar(int nblk) {
    __syncthreads();
    if (threadIdx.x == 0) {
        __threadfence();
        int g = g_gen;
        if (atomicAdd(&g_arr, 1) == nblk - 1) {
            g_arr = 0;
            __threadfence();
            g_gen = g + 1;
        } else {
            while (g_gen == g) __nanosleep(64);
        }
    }
    __syncthreads();
}

// Block-wide exclusive scan over TPB ints. All threads participate; all shfls
// execute warp-uniformly with full masks.
static __device__ __forceinline__ int block_excl_scan(int v, int tid,
                                                      int* s_warp, int* total) {
    int lane = tid & 31, w = tid >> 5;
    int x = v;
#pragma unroll
    for (int o = 1; o < 32; o <<= 1) {
        int y = __shfl_up_sync(0xFFFFFFFFu, x, o);
        if (lane >= o) x += y;
    }
    if (lane == 31) s_warp[w] = x;
    __syncthreads();
    if (w == 0) {                      // whole warp 0 executes
        int y = (lane < NW) ? s_warp[lane] : 0;
#pragma unroll
        for (int o = 1; o < NW; o <<= 1) {
            int z = __shfl_up_sync(0xFFFFFFFFu, y, o);
            if (lane >= o) y += z;
        }
        if (lane < NW) s_warp[lane] = y;
    }
    __syncthreads();
    int base = w ? s_warp[w - 1] : 0;
    *total = s_warp[NW - 1];
    __syncthreads();                   // allow s_warp reuse
    return base + x - v;
}

static __device__ __forceinline__ int cell_of(float v, float o, float inv) {
    return min(G - 1, max(0, (int)((v - o) * inv)));
}

// ---------------------------------------------------------------------------
__global__ __launch_bounds__(TPB) void chamfer_fused(
    const float* __restrict__ A, int na,
    const float* __restrict__ B, int nb,
    float* __restrict__ out, int nblk)
{
    const int tid  = threadIdx.x;
    const int b    = blockIdx.x;
    const int gsz  = nblk * TPB;
    const int gtid = b * TPB + tid;
    const int total = na + nb;

    __shared__ int      s_warp[NW];
    __shared__ unsigned s_bb[4];
    __shared__ int      s_base;

    // ---------------- P0: zero counts, bbox partials, init out ----------------
    for (int i = gtid; i < TC; i += gsz) g_cnt[i] = 0;
    if (gtid == 0) { out[0] = 0.0f; g_off[TC] = total; }

    unsigned mnx = 0xFFFFFFFFu, mny = 0xFFFFFFFFu, mxx = 0u, mxy = 0u;
    for (int i = gtid; i < total; i += gsz) {
        const float2 p = (i < na) ? ((const float2*)A)[i]
                                  : ((const float2*)B)[i - na];
        unsigned ux = f2ord(p.x), uy = f2ord(p.y);
        mnx = min(mnx, ux); mny = min(mny, uy);
        mxx = max(mxx, ux); mxy = max(mxy, uy);
    }
#pragma unroll
    for (int o = 16; o > 0; o >>= 1) {
        mnx = min(mnx, __shfl_down_sync(0xFFFFFFFFu, mnx, o));
        mny = min(mny, __shfl_down_sync(0xFFFFFFFFu, mny, o));
        mxx = max(mxx, __shfl_down_sync(0xFFFFFFFFu, mxx, o));
        mxy = max(mxy, __shfl_down_sync(0xFFFFFFFFu, mxy, o));
    }
    {
        __shared__ unsigned sw[4][NW];
        int lane = tid & 31, w = tid >> 5;
        if (lane == 0) { sw[0][w] = mnx; sw[1][w] = mny; sw[2][w] = mxx; sw[3][w] = mxy; }
        __syncthreads();
        if (w == 0) {                  // whole warp executes; neutral fill
            mnx = (lane < NW) ? sw[0][lane] : 0xFFFFFFFFu;
            mny = (lane < NW) ? sw[1][lane] : 0xFFFFFFFFu;
            mxx = (lane < NW) ? sw[2][lane] : 0u;
            mxy = (lane < NW) ? sw[3][lane] : 0u;
#pragma unroll
            for (int o = 16; o > 0; o >>= 1) {
                mnx = min(mnx, __shfl_down_sync(0xFFFFFFFFu, mnx, o));
                mny = min(mny, __shfl_down_sync(0xFFFFFFFFu, mny, o));
                mxx = max(mxx, __shfl_down_sync(0xFFFFFFFFu, mxx, o));
                mxy = max(mxy, __shfl_down_sync(0xFFFFFFFFu, mxy, o));
            }
            if (lane == 0) {
                g_blkbox[b][0] = mnx; g_blkbox[b][1] = mny;
                g_blkbox[b][2] = mxx; g_blkbox[b][3] = mxy;
            }
        }
    }
    gridbar(nblk);

    // ---------------- grid params (once; kept in registers) ----------------
    if (tid < 32) {                    // whole warp 0
        unsigned a0 = 0xFFFFFFFFu, a1 = 0xFFFFFFFFu, a2 = 0u, a3 = 0u;
        for (int k = tid; k < nblk; k += 32) {
            a0 = min(a0, g_blkbox[k][0]); a1 = min(a1, g_blkbox[k][1]);
            a2 = max(a2, g_blkbox[k][2]); a3 = max(a3, g_blkbox[k][3]);
        }
#pragma unroll
        for (int o = 16; o > 0; o >>= 1) {
            a0 = min(a0, __shfl_down_sync(0xFFFFFFFFu, a0, o));
            a1 = min(a1, __shfl_down_sync(0xFFFFFFFFu, a1, o));
            a2 = max(a2, __shfl_down_sync(0xFFFFFFFFu, a2, o));
            a3 = max(a3, __shfl_down_sync(0xFFFFFFFFu, a3, o));
        }
        if (tid == 0) { s_bb[0] = a0; s_bb[1] = a1; s_bb[2] = a2; s_bb[3] = a3; }
    }
    __syncthreads();
    const float x0 = ord2f(s_bb[0]);
    const float y0 = ord2f(s_bb[1]);
    const float L  = fmaxf(fmaxf(ord2f(s_bb[2]) - x0, ord2f(s_bb[3]) - y0), 1e-20f);
    const float cs = L / (float)G;
    const float inv = (float)G / L;

    // ---------------- P1: bin points (cell id + rank) ----------------
    for (int i = gtid; i < total; i += gsz) {
        const float2 p = (i < na) ? ((const float2*)A)[i]
                                  : ((const float2*)B)[i - na];
        int s = (i < na) ? 0 : 1;
        int c = s * NCELL + cell_of(p.y, y0, inv) * G + cell_of(p.x, x0, inv);
        g_cid[i]  = c;
        g_rank[i] = atomicAdd(&g_cnt[c], 1);
    }
    gridbar(nblk);

    // ---------------- P2: per-block chunk scan ----------------
    const int cpb = (TC + nblk - 1) / nblk;       // <= TPB for nblk >= 128
    const int idx = b * cpb + tid;
    int v = (tid < cpb && idx < TC) ? g_cnt[idx] : 0;
    int btot;
    int excl = block_excl_scan(v, tid, s_warp, &btot);
    if (tid == 0) g_blksum[b] = btot;
    gridbar(nblk);

    // ---------------- P3: block bases -> CSR offsets ----------------
    {
        int bv = (tid < nblk) ? g_blksum[tid] : 0;
        int t2;
        int e2 = block_excl_scan(bv, tid, s_warp, &t2);
        if (tid == b) s_base = e2;
        __syncthreads();
        if (tid < cpb && idx < TC) g_off[idx] = s_base + excl;
    }
    gridbar(nblk);

    // ---------------- P4: scatter fill ----------------
    for (int i = gtid; i < total; i += gsz) {
        const float2 p = (i < na) ? ((const float2*)A)[i]
                                  : ((const float2*)B)[i - na];
        g_pts[g_off[g_cid[i]] + g_rank[i]] = p;
    }
    gridbar(nblk);

    // ---------------- P5: query, 4 lanes per query ----------------
    float acc = 0.0f;
    const int ntask = 4 * total;
    const unsigned gmask = 0xFu << ((tid & 31) & 28);   // this thread's 4-lane group

    for (int task = gtid; task < ntask; task += gsz) {
        int q   = task >> 2;
        int sub = task & 3;
        int t   = (q < na) ? 1 : 0;                     // target = other set
        float2 Q = g_pts[q];                            // sorted -> warp-coherent
        int cx = cell_of(Q.x, x0, inv);
        int cy = cell_of(Q.y, y0, inv);
        const int* __restrict__ off = g_off + t * NCELL;

        float best = CUDART_INF_F;

        // 3x3 neighborhood: three contiguous CSR row segments, lane-strided.
        {
            int xlo = max(cx - 1, 0), xhi = min(cx + 1, G - 1);
            int ylo = max(cy - 1, 0), yhi = min(cy + 1, G - 1);
            for (int yy = ylo; yy <= yhi; yy++) {
                int s0 = off[yy * G + xlo], e0 = off[yy * G + xhi + 1];
                for (int k = s0 + sub; k < e0; k += 4) {
                    float2 p = g_pts[k];
                    float dx = Q.x - p.x, dy = Q.y - p.y;
                    best = fminf(best, fmaf(dx, dx, dy * dy));
                }
            }
        }
        best = fminf(best, __shfl_xor_sync(gmask, best, 1));
        best = fminf(best, __shfl_xor_sync(gmask, best, 2));

        // Exact ring expansion: before ring r, unscanned pts >= (r-1)*cs away.
        // Break decision uses the group-combined best -> lanes stay converged.
        for (int r = 2; r < G; r++) {
            float bb = (float)(r - 1) * cs;
            if (best <= bb * bb) break;
            int xlo = max(cx - r, 0), xhi = min(cx + r, G - 1);
            if (cy - r >= 0) {
                int row = (cy - r) * G;
                int s0 = off[row + xlo], e0 = off[row + xhi + 1];
                for (int k = s0 + sub; k < e0; k += 4) {
                    float2 p = g_pts[k];
                    float dx = Q.x - p.x, dy = Q.y - p.y;
                    best = fminf(best, fmaf(dx, dx, dy * dy));
                }
            }
            if (cy + r <= G - 1) {
                int row = (cy + r) * G;
                int s0 = off[row + xlo], e0 = off[row + xhi + 1];
                for (int k = s0 + sub; k < e0; k += 4) {
                    float2 p = g_pts[k];
                    float dx = Q.x - p.x, dy = Q.y - p.y;
                    best = fminf(best, fmaf(dx, dx, dy * dy));
                }
            }
            int ylo = max(cy - r + 1, 0), yhi = min(cy + r - 1, G - 1);
            if (cx - r >= 0) {
                for (int yy = ylo; yy <= yhi; yy++) {
                    int s0 = off[yy * G + cx - r], e0 = off[yy * G + cx - r + 1];
                    for (int k = s0 + sub; k < e0; k += 4) {
                        float2 p = g_pts[k];
                        float dx = Q.x - p.x, dy = Q.y - p.y;
                        best = fminf(best, fmaf(dx, dx, dy * dy));
                    }
                }
            }
            if (cx + r <= G - 1) {
                for (int yy = ylo; yy <= yhi; yy++) {
                    int s0 = off[yy * G + cx + r], e0 = off[yy * G + cx + r + 1];
                    for (int k = s0 + sub; k < e0; k += 4) {
                        float2 p = g_pts[k];
                        float dx = Q.x - p.x, dy = Q.y - p.y;
                        best = fminf(best, fmaf(dx, dx, dy * dy));
                    }
                }
            }
            best = fminf(best, __shfl_xor_sync(gmask, best, 1));
            best = fminf(best, __shfl_xor_sync(gmask, best, 2));
        }
        if (sub == 0) acc += sqrtf(best);
    }

    // Block sum -> one atomicAdd per block (warp 0 fully executes stage 2).
#pragma unroll
    for (int o = 16; o > 0; o >>= 1)
        acc += __shfl_down_sync(0xFFFFFFFFu, acc, o);
    {
        __shared__ float ws[NW];
        int lane = tid & 31, w = tid >> 5;
        if (lane == 0) ws[w] = acc;
        __syncthreads();
        if (w == 0) {
            acc = (lane < NW) ? ws[lane] : 0.0f;
#pragma unroll
            for (int o = 16; o > 0; o >>= 1)
                acc += __shfl_down_sync(0xFFFFFFFFu, acc, o);
            if (lane == 0) atomicAdd(out, acc);
        }
    }
}

// ---------------------------------------------------------------------------
extern "C" void kernel_launch(void* const* d_in, const int* in_sizes, int n_in,
                              void* d_out, int out_size) {
    const float* A = (const float*)d_in[0];
    const float* B = (const float*)d_in[1];
    int na = in_sizes[0] / 2;
    int nb = in_sizes[1] / 2;
    float* out = (float*)d_out;

    int sms = 0;
    if (cudaDeviceGetAttribute(&sms, cudaDevAttrMultiProcessorCount, 0) != cudaSuccess
        || sms <= 0) sms = 148;
    int nblk = sms;
    if (nblk > MAXBLK) nblk = MAXBLK;
    if (nblk < 128)    nblk = 128;     // keep cpb <= TPB for the chunk scan

    chamfer_fused<<<nblk, TPB>>>(A, na, B, nb, out, nblk);
}

// round 6
// speedup vs baseline: 5.4895x; 1.3088x over previous
#include <cuda_runtime.h>
#include <math_constants.h>

// ============================================================================
// Chamfer loss: ONE persistent kernel, exact uniform-grid NN with CSR layout.
// Grid = #SMs (co-resident) with software grid barriers. TPB=512.
// P0 bbox+zero | P1 bin | P2 chunk scan | P3 offsets | P4 fill | P5 query.
// P5: 4 lanes/query. 3x3 fast path (exact when best <= cs^2), else EXACT
// row-band scan: rows cy+-dy over x in [cx-W,cx+W]; each row-range is ONE
// contiguous CSR segment (2 offset loads). Stop when (dy-1)*cs >= sqrt(best);
// width exact when W*cs >= sqrt(best), else widen & rescan (rare).
// ============================================================================

#define G      128
#define NCELL  (G * G)
#define TC     (2 * NCELL)
#define TMAX   65536
#define TPB    512
#define NW     (TPB / 32)
#define MAXBLK 256

__device__ int          g_arr;
__device__ volatile int g_gen;
__device__ unsigned     g_blkbox[MAXBLK][4];
__device__ int          g_blksum[MAXBLK];
__device__ int          g_cnt[TC];
__device__ int          g_off[TC + 1];
__device__ int          g_cid[TMAX];
__device__ int          g_rank[TMAX];
__device__ float2       g_pts[TMAX];

static __device__ __forceinline__ unsigned f2ord(float f) {
    int b = __float_as_int(f);
    return (unsigned)b ^ (b < 0 ? 0xFFFFFFFFu : 0x80000000u);
}
static __device__ __forceinline__ float ord2f(unsigned u) {
    int b = (u & 0x80000000u) ? (int)(u ^ 0x80000000u) : (int)(~u);
    return __int_as_float(b);
}

static __device__ __forceinline__ void gridbar(int nblk) {
    __syncthreads();
    if (threadIdx.x == 0) {
        __threadfence();
        int g = g_gen;
        if (atomicAdd(&g_arr, 1) == nblk - 1) {
            g_arr = 0;
            __threadfence();
            g_gen = g + 1;
        } else {
            while (g_gen == g) __nanosleep(64);
        }
    }
    __syncthreads();
}

// Block-wide exclusive scan; warp-uniform shfls, full masks.
static __device__ __forceinline__ int block_excl_scan(int v, int tid,
                                                      int* s_warp, int* total) {
    int lane = tid & 31, w = tid >> 5;
    int x = v;
#pragma unroll
    for (int o = 1; o < 32; o <<= 1) {
        int y = __shfl_up_sync(0xFFFFFFFFu, x, o);
        if (lane >= o) x += y;
    }
    if (lane == 31) s_warp[w] = x;
    __syncthreads();
    if (w == 0) {
        int y = (lane < NW) ? s_warp[lane] : 0;
#pragma unroll
        for (int o = 1; o < NW; o <<= 1) {
            int z = __shfl_up_sync(0xFFFFFFFFu, y, o);
            if (lane >= o) y += z;
        }
        if (lane < NW) s_warp[lane] = y;
    }
    __syncthreads();
    int base = w ? s_warp[w - 1] : 0;
    *total = s_warp[NW - 1];
    __syncthreads();
    return base + x - v;
}

static __device__ __forceinline__ int cell_of(float v, float o, float inv) {
    return min(G - 1, max(0, (int)((v - o) * inv)));
}

// ---------------------------------------------------------------------------
__global__ __launch_bounds__(TPB) void chamfer_fused(
    const float* __restrict__ A, int na,
    const float* __restrict__ B, int nb,
    float* __restrict__ out, int nblk)
{
    const int tid  = threadIdx.x;
    const int b    = blockIdx.x;
    const int gsz  = nblk * TPB;
    const int gtid = b * TPB + tid;
    const int total = na + nb;

    __shared__ int      s_warp[NW];
    __shared__ unsigned s_bb[4];
    __shared__ int      s_base;

    // ---------------- P0: zero counts, bbox partials, init out ----------------
    for (int i = gtid; i < TC; i += gsz) g_cnt[i] = 0;
    if (gtid == 0) { out[0] = 0.0f; g_off[TC] = total; }

    unsigned mnx = 0xFFFFFFFFu, mny = 0xFFFFFFFFu, mxx = 0u, mxy = 0u;
    for (int i = gtid; i < total; i += gsz) {
        const float2 p = (i < na) ? ((const float2*)A)[i]
                                  : ((const float2*)B)[i - na];
        unsigned ux = f2ord(p.x), uy = f2ord(p.y);
        mnx = min(mnx, ux); mny = min(mny, uy);
        mxx = max(mxx, ux); mxy = max(mxy, uy);
    }
#pragma unroll
    for (int o = 16; o > 0; o >>= 1) {
        mnx = min(mnx, __shfl_down_sync(0xFFFFFFFFu, mnx, o));
        mny = min(mny, __shfl_down_sync(0xFFFFFFFFu, mny, o));
        mxx = max(mxx, __shfl_down_sync(0xFFFFFFFFu, mxx, o));
        mxy = max(mxy, __shfl_down_sync(0xFFFFFFFFu, mxy, o));
    }
    {
        __shared__ unsigned sw[4][NW];
        int lane = tid & 31, w = tid >> 5;
        if (lane == 0) { sw[0][w] = mnx; sw[1][w] = mny; sw[2][w] = mxx; sw[3][w] = mxy; }
        __syncthreads();
        if (w == 0) {
            mnx = (lane < NW) ? sw[0][lane] : 0xFFFFFFFFu;
            mny = (lane < NW) ? sw[1][lane] : 0xFFFFFFFFu;
            mxx = (lane < NW) ? sw[2][lane] : 0u;
            mxy = (lane < NW) ? sw[3][lane] : 0u;
#pragma unroll
            for (int o = 16; o > 0; o >>= 1) {
                mnx = min(mnx, __shfl_down_sync(0xFFFFFFFFu, mnx, o));
                mny = min(mny, __shfl_down_sync(0xFFFFFFFFu, mny, o));
                mxx = max(mxx, __shfl_down_sync(0xFFFFFFFFu, mxx, o));
                mxy = max(mxy, __shfl_down_sync(0xFFFFFFFFu, mxy, o));
            }
            if (lane == 0) {
                g_blkbox[b][0] = mnx; g_blkbox[b][1] = mny;
                g_blkbox[b][2] = mxx; g_blkbox[b][3] = mxy;
            }
        }
    }
    gridbar(nblk);

    // ---------------- grid params ----------------
    if (tid < 32) {
        unsigned a0 = 0xFFFFFFFFu, a1 = 0xFFFFFFFFu, a2 = 0u, a3 = 0u;
        for (int k = tid; k < nblk; k += 32) {
            a0 = min(a0, g_blkbox[k][0]); a1 = min(a1, g_blkbox[k][1]);
            a2 = max(a2, g_blkbox[k][2]); a3 = max(a3, g_blkbox[k][3]);
        }
#pragma unroll
        for (int o = 16; o > 0; o >>= 1) {
            a0 = min(a0, __shfl_down_sync(0xFFFFFFFFu, a0, o));
            a1 = min(a1, __shfl_down_sync(0xFFFFFFFFu, a1, o));
            a2 = max(a2, __shfl_down_sync(0xFFFFFFFFu, a2, o));
            a3 = max(a3, __shfl_down_sync(0xFFFFFFFFu, a3, o));
        }
        if (tid == 0) { s_bb[0] = a0; s_bb[1] = a1; s_bb[2] = a2; s_bb[3] = a3; }
    }
    __syncthreads();
    const float x0 = ord2f(s_bb[0]);
    const float y0 = ord2f(s_bb[1]);
    const float L  = fmaxf(fmaxf(ord2f(s_bb[2]) - x0, ord2f(s_bb[3]) - y0), 1e-20f);
    const float cs = L / (float)G;
    const float inv = (float)G / L;

    // ---------------- P1: bin ----------------
    for (int i = gtid; i < total; i += gsz) {
        const float2 p = (i < na) ? ((const float2*)A)[i]
                                  : ((const float2*)B)[i - na];
        int s = (i < na) ? 0 : 1;
        int c = s * NCELL + cell_of(p.y, y0, inv) * G + cell_of(p.x, x0, inv);
        g_cid[i]  = c;
        g_rank[i] = atomicAdd(&g_cnt[c], 1);
    }
    gridbar(nblk);

    // ---------------- P2: per-block chunk scan ----------------
    const int cpb = (TC + nblk - 1) / nblk;   // <= TPB for nblk >= 64
    const int idx = b * cpb + tid;
    int v = (tid < cpb && idx < TC) ? g_cnt[idx] : 0;
    int btot;
    int excl = block_excl_scan(v, tid, s_warp, &btot);
    if (tid == 0) g_blksum[b] = btot;
    gridbar(nblk);

    // ---------------- P3: block bases -> CSR offsets ----------------
    {
        int bv = (tid < nblk) ? g_blksum[tid] : 0;
        int t2;
        int e2 = block_excl_scan(bv, tid, s_warp, &t2);
        if (tid == b) s_base = e2;
        __syncthreads();
        if (tid < cpb && idx < TC) g_off[idx] = s_base + excl;
    }
    gridbar(nblk);

    // ---------------- P4: scatter fill ----------------
    for (int i = gtid; i < total; i += gsz) {
        const float2 p = (i < na) ? ((const float2*)A)[i]
                                  : ((const float2*)B)[i - na];
        g_pts[g_off[g_cid[i]] + g_rank[i]] = p;
    }
    gridbar(nblk);

    // ---------------- P5: query (4 lanes/query) ----------------
    float acc = 0.0f;
    const int ntask = 4 * total;
    const unsigned gmask = 0xFu << ((tid & 31) & 28);
    const float INF = CUDART_INF_F;

    for (int task = gtid; task < ntask; task += gsz) {
        int q   = task >> 2;
        int sub = task & 3;
        float2 Q = g_pts[q];
        int cx = cell_of(Q.x, x0, inv);
        int cy = cell_of(Q.y, y0, inv);
        const int* __restrict__ off = g_off + ((q < na) ? 1 : 0) * NCELL;

        float best = INF;

        // --- fast path: 3x3 (3 contiguous row segments, offsets prefetched) ---
        {
            int xlo = max(cx - 1, 0), xhi = min(cx + 1, G - 1);
            int ylo = max(cy - 1, 0), yhi = min(cy + 1, G - 1);
            int sg[3], eg[3], nr = 0;
            for (int yy = ylo; yy <= yhi; yy++) {
                sg[nr] = off[yy * G + xlo];
                eg[nr] = off[yy * G + xhi + 1];
                nr++;
            }
            for (int r = 0; r < nr; r++)
                for (int k = sg[r] + sub; k < eg[r]; k += 4) {
                    float2 p = g_pts[k];
                    float dx = Q.x - p.x, dy = Q.y - p.y;
                    best = fminf(best, fmaf(dx, dx, dy * dy));
                }
        }
        best = fminf(best, __shfl_xor_sync(gmask, best, 1));
        best = fminf(best, __shfl_xor_sync(gmask, best, 2));

        // --- exact escape: row-band scan (group-uniform control flow) ---
        if (!(best <= cs * cs)) {
            int W = 12;
            for (;;) {
                if (best < INF) {
                    int Wn = (int)(sqrtf(best) * inv) + 2;
                    if (Wn > W) W = Wn;
                }
                if (W > G - 1) W = G - 1;
                int xlo = max(cx - W, 0), xhi = min(cx + W, G - 1);

                for (int dy = 0; dy < G; dy++) {
                    if (dy >= 1 && best < INF) {
                        float bb = (float)(dy - 1) * cs;
                        if (bb * bb >= best) break;      // rows beyond are safe
                    }
                    int yt = cy - dy, yb = cy + dy;
                    if (yt < 0 && yb > G - 1) break;     // grid exhausted
                    if (yt >= 0) {
                        int s0 = off[yt * G + xlo], e0 = off[yt * G + xhi + 1];
                        for (int k = s0 + sub; k < e0; k += 4) {
                            float2 p = g_pts[k];
                            float dx = Q.x - p.x, dyv = Q.y - p.y;
                            best = fminf(best, fmaf(dx, dx, dyv * dyv));
                        }
                    }
                    if (dy > 0 && yb <= G - 1) {
                        int s0 = off[yb * G + xlo], e0 = off[yb * G + xhi + 1];
                        for (int k = s0 + sub; k < e0; k += 4) {
                            float2 p = g_pts[k];
                            float dx = Q.x - p.x, dyv = Q.y - p.y;
                            best = fminf(best, fmaf(dx, dx, dyv * dyv));
                        }
                    }
                    best = fminf(best, __shfl_xor_sync(gmask, best, 1));
                    best = fminf(best, __shfl_xor_sync(gmask, best, 2));
                }

                if (best < INF) {
                    float wb = (float)W * cs;            // width sufficiency
                    if (wb * wb >= best) break;
                } else if (W >= G - 1) {
                    break;                               // unreachable (nonempty set)
                }
                W <<= 1;                                 // widen & rescan (rare)
            }
        }

        if (sub == 0) acc += sqrtf(best);
    }

    // Block sum -> one atomicAdd per block.
#pragma unroll
    for (int o = 16; o > 0; o >>= 1)
        acc += __shfl_down_sync(0xFFFFFFFFu, acc, o);
    {
        __shared__ float ws[NW];
        int lane = tid & 31, w = tid >> 5;
        if (lane == 0) ws[w] = acc;
        __syncthreads();
        if (w == 0) {
            acc = (lane < NW) ? ws[lane] : 0.0f;
#pragma unroll
            for (int o = 16; o > 0; o >>= 1)
                acc += __shfl_down_sync(0xFFFFFFFFu, acc, o);
            if (lane == 0) atomicAdd(out, acc);
        }
    }
}

// ---------------------------------------------------------------------------
extern "C" void kernel_launch(void* const* d_in, const int* in_sizes, int n_in,
                              void* d_out, int out_size) {
    const float* A = (const float*)d_in[0];
    const float* B = (const float*)d_in[1];
    int na = in_sizes[0] / 2;
    int nb = in_sizes[1] / 2;
    float* out = (float*)d_out;

    int sms = 0;
    if (cudaDeviceGetAttribute(&sms, cudaDevAttrMultiProcessorCount, 0) != cudaSuccess
        || sms <= 0) sms = 148;
    int nblk = sms;
    if (nblk > MAXBLK) nblk = MAXBLK;
    if (nblk < 64)     nblk = 64;      // keep cpb <= TPB for the chunk scan

    chamfer_fused<<<nblk, TPB>>>(A, na, B, nb, out, nblk);
}